// round 1
// baseline (speedup 1.0000x reference)
#include <cuda_runtime.h>
#include <cuda_bf16.h>
#include <math_constants.h>

#define N_NODES  2000000
#define DEPTH    128
#define N_GRAPHS 4096
#define ROWS_PER_BLOCK 512
#define GT 16   // graphs per block in MLP kernel

// Scratch accumulators (allocation-free: __device__ globals)
__device__ float g_sum[N_GRAPHS * DEPTH];
__device__ float g_max[N_GRAPHS * DEPTH];
__device__ int   g_cnt[N_GRAPHS];

__device__ __forceinline__ void atomicMaxF(float* addr, float v) {
    // standard int/uint monotonic-bits trick (no NaNs in input)
    if (v >= 0.0f) atomicMax((int*)addr, __float_as_int(v));
    else           atomicMin((unsigned int*)addr, __float_as_uint(v));
}

__global__ void init_kernel() {
    int idx = blockIdx.x * blockDim.x + threadIdx.x;
    if (idx < N_GRAPHS * DEPTH) {
        g_sum[idx] = 0.0f;
        g_max[idx] = -CUDART_INF_F;
    }
    if (idx < N_GRAPHS) g_cnt[idx] = 0;
}

// One block = 512 consecutive rows, thread d = feature dim d.
// batch is sorted -> contiguous segments; accumulate in registers,
// flush with atomics only on segment change.
__global__ __launch_bounds__(DEPTH) void reduce_kernel(
    const float* __restrict__ x, const int* __restrict__ batch)
{
    __shared__ int s_batch[ROWS_PER_BLOCK];
    const int d    = threadIdx.x;
    const int base = blockIdx.x * ROWS_PER_BLOCK;
    const int nrow = min(ROWS_PER_BLOCK, N_NODES - base);

    for (int i = threadIdx.x; i < nrow; i += DEPTH)
        s_batch[i] = batch[base + i];
    __syncthreads();

    int   cur  = s_batch[0];
    float lsum = 0.0f;
    float lmax = -CUDART_INF_F;
    int   lcnt = 0;

    for (int r0 = 0; r0 < nrow; r0 += 8) {
        float v[8];
        #pragma unroll
        for (int i = 0; i < 8; i++) {
            int row = base + r0 + i;
            v[i] = (r0 + i < nrow) ? __ldcs(&x[(size_t)row * DEPTH + d]) : 0.0f;
        }
        #pragma unroll
        for (int i = 0; i < 8; i++) {
            if (r0 + i < nrow) {
                int g = s_batch[r0 + i];
                if (g != cur) {
                    atomicAdd(&g_sum[cur * DEPTH + d], lsum);
                    atomicMaxF(&g_max[cur * DEPTH + d], lmax);
                    if (d == 0) atomicAdd(&g_cnt[cur], lcnt);
                    cur = g; lsum = 0.0f; lmax = -CUDART_INF_F; lcnt = 0;
                }
                lsum += v[i];
                lmax  = fmaxf(lmax, v[i]);
                lcnt++;
            }
        }
    }
    // tail flush (block always has >=1 valid row)
    atomicAdd(&g_sum[cur * DEPTH + d], lsum);
    atomicMaxF(&g_max[cur * DEPTH + d], lmax);
    if (d == 0) atomicAdd(&g_cnt[cur], lcnt);
}

// MLP over 4096 graphs: h = leaky_relu(concat[mx,mean,sum] @ W1^T + b1);
// out = h @ W2^T + b2. One block handles GT graphs; thread j owns output dim j.
__global__ __launch_bounds__(DEPTH) void mlp_kernel(
    const float* __restrict__ W1, const float* __restrict__ b1,
    const float* __restrict__ W2, const float* __restrict__ b2,
    float* __restrict__ out)
{
    __shared__ float sc[GT][3 * DEPTH]; // concat vectors  (24 KB)
    __shared__ float sh[GT][DEPTH];     // hidden vectors  ( 8 KB)
    const int j  = threadIdx.x;
    const int g0 = blockIdx.x * GT;

    #pragma unroll
    for (int g = 0; g < GT; g++) {
        int gg = g0 + g;
        float s  = g_sum[gg * DEPTH + j];
        int   c  = g_cnt[gg];
        float m  = g_max[gg * DEPTH + j];
        float mx = (c > 0) ? m : 0.0f;
        float mean = s / fmaxf((float)c, 1.0f);
        sc[g][j]             = mx;
        sc[g][DEPTH + j]     = mean;
        sc[g][2 * DEPTH + j] = s;
    }
    __syncthreads();

    float acc[GT];
    {
        float bb = b1[j];
        #pragma unroll
        for (int g = 0; g < GT; g++) acc[g] = bb;
        const float4* w1r = (const float4*)(W1 + (size_t)j * (3 * DEPTH));
        #pragma unroll 4
        for (int k4 = 0; k4 < (3 * DEPTH) / 4; k4++) {
            float4 w = w1r[k4];
            #pragma unroll
            for (int g = 0; g < GT; g++) {
                float4 c = *(const float4*)&sc[g][k4 * 4];
                acc[g] += w.x * c.x + w.y * c.y + w.z * c.z + w.w * c.w;
            }
        }
        #pragma unroll
        for (int g = 0; g < GT; g++) {
            float h = acc[g];
            sh[g][j] = (h > 0.0f) ? h : 0.01f * h;   // leaky_relu slope 0.01
        }
    }
    __syncthreads();
    {
        float bb = b2[j];
        #pragma unroll
        for (int g = 0; g < GT; g++) acc[g] = bb;
        const float4* w2r = (const float4*)(W2 + (size_t)j * DEPTH);
        #pragma unroll 4
        for (int k4 = 0; k4 < DEPTH / 4; k4++) {
            float4 w = w2r[k4];
            #pragma unroll
            for (int g = 0; g < GT; g++) {
                float4 h = *(const float4*)&sh[g][k4 * 4];
                acc[g] += w.x * h.x + w.y * h.y + w.z * h.z + w.w * h.w;
            }
        }
        #pragma unroll
        for (int g = 0; g < GT; g++)
            out[(size_t)(g0 + g) * DEPTH + j] = acc[g];
    }
}

extern "C" void kernel_launch(void* const* d_in, const int* in_sizes, int n_in,
                              void* d_out, int out_size)
{
    // Identify inputs by element count (robust to whether the scalar
    // output_dim appears as an input).
    const float* x  = nullptr; const int* batch = nullptr;
    const float* W1 = nullptr; const float* b1 = nullptr;
    const float* W2 = nullptr; const float* b2 = nullptr;
    for (int i = 0; i < n_in; i++) {
        long s = in_sizes[i];
        if      (s == (long)N_NODES * DEPTH)  x     = (const float*)d_in[i];
        else if (s == (long)N_NODES)          batch = (const int*)  d_in[i];
        else if (s == (long)DEPTH * 3 * DEPTH) W1   = (const float*)d_in[i];
        else if (s == (long)DEPTH * DEPTH)     W2   = (const float*)d_in[i];
        else if (s == (long)DEPTH) { if (!b1) b1 = (const float*)d_in[i];
                                     else     b2 = (const float*)d_in[i]; }
        // s == 1 (output_dim scalar) ignored: N_GRAPHS is compile-time
    }

    init_kernel<<<(N_GRAPHS * DEPTH + 255) / 256, 256>>>();

    int nblocks = (N_NODES + ROWS_PER_BLOCK - 1) / ROWS_PER_BLOCK;
    reduce_kernel<<<nblocks, DEPTH>>>(x, batch);

    mlp_kernel<<<N_GRAPHS / GT, DEPTH>>>(W1, b1, W2, b2, (float*)d_out);
}

// round 2
// speedup vs baseline: 1.0595x; 1.0595x over previous
#include <cuda_runtime.h>
#include <cuda_bf16.h>
#include <math_constants.h>

#define N_NODES  2000000
#define DEPTH    128
#define N_GRAPHS 4096
#define ROWS_PER_BLOCK 512
#define THREADS_R 256
#define ROWS_PER_WARP 64      // 512 rows / 8 warps
#define GT 16                 // graphs per block in MLP kernel

// Scratch accumulators (allocation-free: __device__ globals)
__device__ float g_sum[N_GRAPHS * DEPTH];
__device__ float g_max[N_GRAPHS * DEPTH];
__device__ int   g_cnt[N_GRAPHS];

__device__ __forceinline__ void atomicMaxF(float* addr, float v) {
    // monotonic-bits trick (inputs are finite, no NaNs)
    if (v >= 0.0f) atomicMax((int*)addr, __float_as_int(v));
    else           atomicMin((unsigned int*)addr, __float_as_uint(v));
}

// Vectorized init: 131072 float4 stores per array
__global__ __launch_bounds__(256) void init_kernel() {
    int i = blockIdx.x * 256 + threadIdx.x;           // grid = 512 blocks
    float4 z = make_float4(0.f, 0.f, 0.f, 0.f);
    float4 m = make_float4(-CUDART_INF_F, -CUDART_INF_F, -CUDART_INF_F, -CUDART_INF_F);
    ((float4*)g_sum)[i] = z;
    ((float4*)g_max)[i] = m;
    if (i < N_GRAPHS) g_cnt[i] = 0;
}

// One block = 512 consecutive rows; warp w owns 64 contiguous rows.
// Lane c owns float4 column c (features 4c..4c+3). batch is sorted ->
// contiguous segments; accumulate in registers, flush atomics at boundaries.
__global__ __launch_bounds__(THREADS_R) void reduce_kernel(
    const float4* __restrict__ x4, const int* __restrict__ batch)
{
    __shared__ int s_batch[ROWS_PER_BLOCK];
    const int tid  = threadIdx.x;
    const int w    = tid >> 5;
    const int c    = tid & 31;
    const int base = blockIdx.x * ROWS_PER_BLOCK;
    const int nrow = min(ROWS_PER_BLOCK, N_NODES - base);   // 512 or 128

    for (int i = tid; i < nrow; i += THREADS_R)
        s_batch[i] = batch[base + i];
    __syncthreads();

    const int rstart = w * ROWS_PER_WARP;
    if (rstart >= nrow) return;          // last block: warps 2..7 idle
    // nrow is always a multiple of 64 here -> each active warp has exactly 64 rows

    int    cur  = s_batch[rstart];
    float4 ls   = make_float4(0.f, 0.f, 0.f, 0.f);
    float4 lm   = make_float4(-CUDART_INF_F, -CUDART_INF_F, -CUDART_INF_F, -CUDART_INF_F);
    int    lcnt = 0;

    for (int r = rstart; r < rstart + ROWS_PER_WARP; r += 4) {
        float4 v[4];
        #pragma unroll
        for (int i = 0; i < 4; i++)
            v[i] = __ldcs(&x4[(size_t)(base + r + i) * 32 + c]);

        #pragma unroll
        for (int i = 0; i < 4; i++) {
            int g = s_batch[r + i];
            if (g != cur) {
                float* ps = &g_sum[cur * DEPTH + 4 * c];
                atomicAdd(ps + 0, ls.x); atomicAdd(ps + 1, ls.y);
                atomicAdd(ps + 2, ls.z); atomicAdd(ps + 3, ls.w);
                float* pm = &g_max[cur * DEPTH + 4 * c];
                atomicMaxF(pm + 0, lm.x); atomicMaxF(pm + 1, lm.y);
                atomicMaxF(pm + 2, lm.z); atomicMaxF(pm + 3, lm.w);
                if (c == 0) atomicAdd(&g_cnt[cur], lcnt);
                cur = g; lcnt = 0;
                ls = make_float4(0.f, 0.f, 0.f, 0.f);
                lm = make_float4(-CUDART_INF_F, -CUDART_INF_F, -CUDART_INF_F, -CUDART_INF_F);
            }
            ls.x += v[i].x; ls.y += v[i].y; ls.z += v[i].z; ls.w += v[i].w;
            lm.x = fmaxf(lm.x, v[i].x); lm.y = fmaxf(lm.y, v[i].y);
            lm.z = fmaxf(lm.z, v[i].z); lm.w = fmaxf(lm.w, v[i].w);
            lcnt++;
        }
    }
    // tail flush
    {
        float* ps = &g_sum[cur * DEPTH + 4 * c];
        atomicAdd(ps + 0, ls.x); atomicAdd(ps + 1, ls.y);
        atomicAdd(ps + 2, ls.z); atomicAdd(ps + 3, ls.w);
        float* pm = &g_max[cur * DEPTH + 4 * c];
        atomicMaxF(pm + 0, lm.x); atomicMaxF(pm + 1, lm.y);
        atomicMaxF(pm + 2, lm.z); atomicMaxF(pm + 3, lm.w);
        if (c == 0) atomicAdd(&g_cnt[cur], lcnt);
    }
}

// MLP over 4096 graphs: h = leaky_relu(concat[mx,mean,sum] @ W1^T + b1);
// out = h @ W2^T + b2. One block handles GT graphs; thread j owns output dim j.
__global__ __launch_bounds__(DEPTH) void mlp_kernel(
    const float* __restrict__ W1, const float* __restrict__ b1,
    const float* __restrict__ W2, const float* __restrict__ b2,
    float* __restrict__ out)
{
    __shared__ float sc[GT][3 * DEPTH]; // concat vectors  (24 KB)
    __shared__ float sh[GT][DEPTH];     // hidden vectors  ( 8 KB)
    const int j  = threadIdx.x;
    const int g0 = blockIdx.x * GT;

    #pragma unroll
    for (int g = 0; g < GT; g++) {
        int gg = g0 + g;
        float s  = g_sum[gg * DEPTH + j];
        int   cnt = g_cnt[gg];
        float m  = g_max[gg * DEPTH + j];
        float mx = (cnt > 0) ? m : 0.0f;
        float mean = s / fmaxf((float)cnt, 1.0f);
        sc[g][j]             = mx;
        sc[g][DEPTH + j]     = mean;
        sc[g][2 * DEPTH + j] = s;
    }
    __syncthreads();

    float acc[GT];
    {
        float bb = b1[j];
        #pragma unroll
        for (int g = 0; g < GT; g++) acc[g] = bb;
        const float4* w1r = (const float4*)(W1 + (size_t)j * (3 * DEPTH));
        #pragma unroll 4
        for (int k4 = 0; k4 < (3 * DEPTH) / 4; k4++) {
            float4 w = w1r[k4];
            #pragma unroll
            for (int g = 0; g < GT; g++) {
                float4 cc = *(const float4*)&sc[g][k4 * 4];
                acc[g] += w.x * cc.x + w.y * cc.y + w.z * cc.z + w.w * cc.w;
            }
        }
        #pragma unroll
        for (int g = 0; g < GT; g++) {
            float h = acc[g];
            sh[g][j] = (h > 0.0f) ? h : 0.01f * h;   // leaky_relu slope 0.01
        }
    }
    __syncthreads();
    {
        float bb = b2[j];
        #pragma unroll
        for (int g = 0; g < GT; g++) acc[g] = bb;
        const float4* w2r = (const float4*)(W2 + (size_t)j * DEPTH);
        #pragma unroll 4
        for (int k4 = 0; k4 < DEPTH / 4; k4++) {
            float4 w = w2r[k4];
            #pragma unroll
            for (int g = 0; g < GT; g++) {
                float4 h = *(const float4*)&sh[g][k4 * 4];
                acc[g] += w.x * h.x + w.y * h.y + w.z * h.z + w.w * h.w;
            }
        }
        #pragma unroll
        for (int g = 0; g < GT; g++)
            out[(size_t)(g0 + g) * DEPTH + j] = acc[g];
    }
}

extern "C" void kernel_launch(void* const* d_in, const int* in_sizes, int n_in,
                              void* d_out, int out_size)
{
    const float* x  = nullptr; const int* batch = nullptr;
    const float* W1 = nullptr; const float* b1 = nullptr;
    const float* W2 = nullptr; const float* b2 = nullptr;
    for (int i = 0; i < n_in; i++) {
        long s = in_sizes[i];
        if      (s == (long)N_NODES * DEPTH)   x     = (const float*)d_in[i];
        else if (s == (long)N_NODES)           batch = (const int*)  d_in[i];
        else if (s == (long)DEPTH * 3 * DEPTH) W1    = (const float*)d_in[i];
        else if (s == (long)DEPTH * DEPTH)     W2    = (const float*)d_in[i];
        else if (s == (long)DEPTH) { if (!b1) b1 = (const float*)d_in[i];
                                     else     b2 = (const float*)d_in[i]; }
    }

    init_kernel<<<(N_GRAPHS * DEPTH / 4) / 256, 256>>>();

    int nblocks = (N_NODES + ROWS_PER_BLOCK - 1) / ROWS_PER_BLOCK;
    reduce_kernel<<<nblocks, THREADS_R>>>((const float4*)x, batch);

    mlp_kernel<<<N_GRAPHS / GT, DEPTH>>>(W1, b1, W2, b2, (float*)d_out);
}